// round 3
// baseline (speedup 1.0000x reference)
#include <cuda_runtime.h>
#include <cuda_bf16.h>

// Quixer quantum transformer block.
// B=16, W=16 words, 8 qubits (DIM=256), 2 ansatz layers (64 gates), DEGREE=3,
// then measure(24) -> ff1(512) -> ff2(50257).

#define VQ   50257
#define EMBQ 512

typedef unsigned long long ull;

// ----------------------------- scratch ------------------------------------
__device__ float2 g_cs[256 * 64];   // per (b,w): (cos(th/2), sin(th/2)) per gate
__device__ float2 g_qcs[32];        // qff gate table (1 layer)
__device__ float2 g_coeffs[16];     // normalized mix coefficients
__device__ float2 g_st[256 * 256];  // per-(b,w) states after sim14
__device__ float2 g_work[16 * 256]; // reduced work state per batch
__device__ float2 g_acc[16 * 256];  // polynomial accumulator
__device__ float  g_fp[16];         // final_probs
__device__ float2 g_hp[512 * 8];    // h packed: hp[k*8+bp] = (h[2bp][k], h[2bp+1][k])

// ----------------------------- f32x2 helpers --------------------------------
__device__ __forceinline__ ull pack2(float a, float b) {
    ull r; asm("mov.b64 %0, {%1, %2};" : "=l"(r) : "f"(a), "f"(b)); return r;
}
__device__ __forceinline__ ull dup2(float a) {
    ull r; asm("mov.b64 %0, {%1, %1};" : "=l"(r) : "f"(a)); return r;
}
__device__ __forceinline__ void ffma2(ull& d, ull a, ull b) {
    asm("fma.rn.f32x2 %0, %1, %2, %0;" : "+l"(d) : "l"(a), "l"(b));
}
__device__ __forceinline__ void unpack2(ull v, float& lo, float& hi) {
    asm("mov.b64 {%0, %1}, %2;" : "=f"(lo), "=f"(hi) : "l"(v));
}

// ----------------------------- gates (128 threads) ---------------------------
// wire w <-> bit (7-w) of amplitude index; stride = 1<<(7-w)
__device__ __forceinline__ void gate_ry(float2* st, float c, float s, int wire) {
    int str = 1 << (7 - wire);
    int p = threadIdx.x;                       // 128 pairs, one per thread
    int i0 = ((p & ~(str - 1)) << 1) | (p & (str - 1));
    int i1 = i0 + str;
    float2 a0 = st[i0], a1 = st[i1];
    st[i0] = make_float2(c * a0.x - s * a1.x, c * a0.y - s * a1.y);
    st[i1] = make_float2(s * a0.x + c * a1.x, s * a0.y + c * a1.y);
    __syncthreads();
}
// controlled RX: [[c,-is],[-is,c]] on target where control bit == 1
__device__ __forceinline__ void gate_crx(float2* st, float c, float s, int cw, int tw) {
    int str = 1 << (7 - tw);
    int cm  = 1 << (7 - cw);
    int p = threadIdx.x;
    int i0 = ((p & ~(str - 1)) << 1) | (p & (str - 1));
    if (i0 & cm) {
        int i1 = i0 + str;
        float2 a0 = st[i0], a1 = st[i1];
        st[i0] = make_float2(c * a0.x + s * a1.y, c * a0.y - s * a1.x);
        st[i1] = make_float2(s * a0.y + c * a1.x, c * a1.y - s * a0.x);
    }
    __syncthreads();
}

__device__ void sim14(float2* st, const float2* cs, int layers) {
    int idx = 0;
    for (int L = 0; L < layers; L++) {
        for (int i = 0; i < 8; i++, idx++)  gate_ry(st, cs[idx].x, cs[idx].y, i);
        for (int i = 7; i >= 0; i--, idx++) gate_crx(st, cs[idx].x, cs[idx].y, i, (i + 1) & 7);
        for (int i = 0; i < 8; i++, idx++)  gate_ry(st, cs[idx].x, cs[idx].y, i);
        for (int i = 0; i < 8; i++, idx++) {          // order: 7, 0, 1, ..., 6
            int ci = (i == 0) ? 7 : (i - 1);
            gate_crx(st, cs[idx].x, cs[idx].y, ci, (ci + 7) & 7);
        }
    }
}

// ----------------------------- k_emb ----------------------------------------
// grid 256 (= b*16+w), 256 threads: wparams = emb @ e2rW^T + b -> (cos,sin)
__global__ void k_emb(const int* __restrict__ x, const float* __restrict__ embW,
                      const float* __restrict__ e2rW, const float* __restrict__ e2rb,
                      const float* __restrict__ mix, const float* __restrict__ qff) {
    __shared__ float emb[EMBQ];
    int tid = threadIdx.x, blk = blockIdx.x;
    int row = x[blk];
    for (int i = tid; i < EMBQ; i += 256) emb[i] = embW[(size_t)row * EMBQ + i];
    __syncthreads();
    int wid = tid >> 5, lane = tid & 31;
    for (int jj = 0; jj < 8; jj++) {
        int j = wid * 8 + jj;
        float p = 0.f;
        const float* wr = e2rW + j * EMBQ;
        for (int k = lane; k < EMBQ; k += 32) p += emb[k] * wr[k];
        #pragma unroll
        for (int o = 16; o; o >>= 1) p += __shfl_xor_sync(0xffffffffu, p, o);
        if (lane == 0) {
            float th = 0.5f * (p + e2rb[j]);
            g_cs[blk * 64 + j] = make_float2(cosf(th), sinf(th));
        }
    }
    if (blk == 0) {
        if (wid == 0) {
            float re = 0.f, im = 0.f, a = 0.f;
            if (lane < 16) { re = mix[2 * lane]; im = mix[2 * lane + 1]; a = sqrtf(re * re + im * im); }
            float s = a;
            #pragma unroll
            for (int o = 16; o; o >>= 1) s += __shfl_xor_sync(0xffffffffu, s, o);
            s = fmaxf(s, 1e-12f);
            if (lane < 16) g_coeffs[lane] = make_float2(re / s, im / s);
        } else if (wid == 1) {
            float th = 0.5f * qff[lane];
            g_qcs[lane] = make_float2(cosf(th), sinf(th));
        }
    }
}

// ----------------------------- k_deg ----------------------------------------
// grid 256 (b*16+w), 128 threads: replicate batch work state, run 2-layer sim14
template <bool FIRST>
__global__ void k_deg() {
    __shared__ float2 st[256];
    __shared__ float2 cs[64];
    int tid = threadIdx.x, blk = blockIdx.x;
    int b = blk >> 4;
    if (FIRST) {
        st[tid]       = make_float2(tid == 0 ? 1.f : 0.f, 0.f);
        st[tid + 128] = make_float2(0.f, 0.f);
    } else {
        st[tid]       = g_work[b * 256 + tid];
        st[tid + 128] = g_work[b * 256 + tid + 128];
    }
    if (tid < 64) cs[tid] = g_cs[blk * 64 + tid];
    __syncthreads();
    sim14(st, cs, 2);
    g_st[blk * 256 + tid]       = st[tid];
    g_st[blk * 256 + tid + 128] = st[tid + 128];
}

// ----------------------------- k_red ----------------------------------------
// grid 16 (batch), 256 threads: word reduction with coeffs + poly accumulate
template <int D>
__global__ void k_red(const float* __restrict__ poly) {
    int i = threadIdx.x, b = blockIdx.x;
    float2 red = make_float2(0.f, 0.f);
    #pragma unroll
    for (int w = 0; w < 16; w++) {
        float2 c = g_coeffs[w];
        float2 s = g_st[(b * 16 + w) * 256 + i];
        red.x += s.x * c.x - s.y * c.y;
        red.y += s.x * c.y + s.y * c.x;
    }
    g_work[b * 256 + i] = red;
    float pd = poly[D];
    float2 a;
    if (D == 1) {
        a = make_float2(pd * red.x + (i == 0 ? poly[0] : 0.f), pd * red.y);
    } else {
        a = g_acc[b * 256 + i];
        a.x += pd * red.x;
        a.y += pd * red.y;
    }
    g_acc[b * 256 + i] = a;
}

// ----------------------------- k_post ---------------------------------------
// grid 16, 128 threads: mixed/normalize, 1-layer sim14, measure XYZ, ff1
__global__ void k_post(const float* __restrict__ poly, const float* __restrict__ ff1W,
                       const float* __restrict__ ff1b) {
    __shared__ float2 st[256];
    __shared__ float2 qcs[32];
    __shared__ float r3[12];
    __shared__ float ex[24];
    int tid = threadIdx.x, b = blockIdx.x;
    int lane = tid & 31, wid = tid >> 5;

    float spoly = fabsf(poly[0]) + fabsf(poly[1]) + fabsf(poly[2]) + fabsf(poly[3]);
    float invp = 1.f / spoly;
    float2 a0 = g_acc[b * 256 + tid];
    float2 a1 = g_acc[b * 256 + tid + 128];
    a0.x *= invp; a0.y *= invp; a1.x *= invp; a1.y *= invp;

    float ns = a0.x * a0.x + a0.y * a0.y + a1.x * a1.x + a1.y * a1.y;
    #pragma unroll
    for (int o = 16; o; o >>= 1) ns += __shfl_xor_sync(0xffffffffu, ns, o);
    if (lane == 0) r3[wid] = ns;
    __syncthreads();
    float fp = sqrtf(r3[0] + r3[1] + r3[2] + r3[3]);
    if (tid == 0) g_fp[b] = fp;
    float inv = 1.f / fmaxf(fp, 1e-12f);
    __syncthreads();  // r3 reuse below

    st[tid]       = make_float2(a0.x * inv, a0.y * inv);
    st[tid + 128] = make_float2(a1.x * inv, a1.y * inv);
    if (tid < 32) qcs[tid] = g_qcs[tid];
    __syncthreads();

    sim14(st, qcs, 1);

    // measure X/Y/Z per wire
    for (int w = 0; w < 8; w++) {
        int str = 1 << (7 - w);
        int i0 = ((tid & ~(str - 1)) << 1) | (tid & (str - 1));
        int i1 = i0 + str;
        float2 A = st[i0], B = st[i1];
        float cr = A.x * B.x + A.y * B.y;
        float ci = A.x * B.y - A.y * B.x;
        float z  = A.x * A.x + A.y * A.y - B.x * B.x - B.y * B.y;
        #pragma unroll
        for (int o = 16; o; o >>= 1) {
            cr += __shfl_xor_sync(0xffffffffu, cr, o);
            ci += __shfl_xor_sync(0xffffffffu, ci, o);
            z  += __shfl_xor_sync(0xffffffffu, z,  o);
        }
        if (lane == 0) { r3[wid] = cr; r3[4 + wid] = ci; r3[8 + wid] = z; }
        __syncthreads();
        if (tid == 0) {
            ex[w]      = 2.f * (r3[0] + r3[1] + r3[2] + r3[3]);
            ex[8 + w]  = 2.f * (r3[4] + r3[5] + r3[6] + r3[7]);
            ex[16 + w] =        r3[8] + r3[9] + r3[10] + r3[11];
        }
        __syncthreads();
    }

    // ff1: h = relu(exps @ ff1W^T + b), write packed pairs for ff2
    for (int j = tid; j < EMBQ; j += 128) {
        float h = ff1b[j];
        const float* wr = ff1W + j * 24;
        #pragma unroll
        for (int m = 0; m < 24; m++) h += ex[m] * wr[m];
        h = fmaxf(h, 0.f);
        float* dst = (float*)&g_hp[j * 8 + (b >> 1)];
        dst[b & 1] = h;
    }
}

// ----------------------------- k_ff2 ----------------------------------------
// op[b][v] = sum_k h[b][k]*W2[v][k] + b2[v].  197 blocks x 64 threads,
// 4 vocab rows/thread, 16 batches packed as 8 f32x2 accumulators.
__global__ void __launch_bounds__(64) k_ff2(const float* __restrict__ W2,
                                            const float* __restrict__ b2,
                                            float* __restrict__ out, int out_size) {
    __shared__ float4 sh[2048];  // hp: per k, 4 float4 = 8 batch pairs
    int tid = threadIdx.x;
    const float4* gp = (const float4*)g_hp;
    for (int i = tid; i < 2048; i += 64) sh[i] = gp[i];
    __syncthreads();

    int base = blockIdx.x * 256;
    int v[4]; bool ok[4];
    #pragma unroll
    for (int r = 0; r < 4; r++) {
        v[r] = base + r * 64 + tid;
        ok[r] = (v[r] < VQ);
        if (!ok[r]) v[r] = VQ - 1;
    }

    ull acc[4][8];
    #pragma unroll
    for (int r = 0; r < 4; r++)
        #pragma unroll
        for (int bp = 0; bp < 8; bp++) acc[r][bp] = 0ull;

    for (int k4 = 0; k4 < 128; k4++) {
        float4 w[4];
        #pragma unroll
        for (int r = 0; r < 4; r++)
            w[r] = *(const float4*)(W2 + (size_t)v[r] * EMBQ + k4 * 4);
        #pragma unroll
        for (int kk = 0; kk < 4; kk++) {
            int k = k4 * 4 + kk;
            ull h[8];
            #pragma unroll
            for (int q = 0; q < 4; q++) {
                float4 f = sh[k * 4 + q];
                h[2 * q]     = pack2(f.x, f.y);
                h[2 * q + 1] = pack2(f.z, f.w);
            }
            #pragma unroll
            for (int r = 0; r < 4; r++) {
                float ws = (kk == 0) ? w[r].x : (kk == 1) ? w[r].y : (kk == 2) ? w[r].z : w[r].w;
                ull wd = dup2(ws);
                #pragma unroll
                for (int bp = 0; bp < 8; bp++) ffma2(acc[r][bp], h[bp], wd);
            }
        }
    }

    #pragma unroll
    for (int r = 0; r < 4; r++) {
        if (!ok[r]) continue;
        float bias = b2[v[r]];
        #pragma unroll
        for (int bp = 0; bp < 8; bp++) {
            float lo, hi;
            unpack2(acc[r][bp], lo, hi);
            out[(size_t)(2 * bp) * VQ + v[r]]     = lo + bias;
            out[(size_t)(2 * bp + 1) * VQ + v[r]] = hi + bias;
        }
    }

    if (blockIdx.x == 0 && tid == 0 && out_size > 16 * VQ) {
        float s = 0.f;
        for (int b = 0; b < 16; b++) s += g_fp[b];
        out[16 * VQ] = s * (1.f / 16.f);
    }
}

// ----------------------------- launch ---------------------------------------
extern "C" void kernel_launch(void* const* d_in, const int* in_sizes, int n_in,
                              void* d_out, int out_size) {
    const int*   x    = (const int*)  d_in[0];
    const float* embW = (const float*)d_in[1];
    const float* e2rW = (const float*)d_in[2];
    const float* e2rb = (const float*)d_in[3];
    const float* poly = (const float*)d_in[4];
    const float* mix  = (const float*)d_in[5];
    const float* qff  = (const float*)d_in[6];
    const float* ff1W = (const float*)d_in[7];
    const float* ff1b = (const float*)d_in[8];
    const float* W2   = (const float*)d_in[9];
    const float* b2   = (const float*)d_in[10];
    float* out = (float*)d_out;

    k_emb<<<256, 256>>>(x, embW, e2rW, e2rb, mix, qff);
    k_deg<true><<<256, 128>>>();
    k_red<1><<<16, 256>>>(poly);
    k_deg<false><<<256, 128>>>();
    k_red<2><<<16, 256>>>(poly);
    k_deg<false><<<256, 128>>>();
    k_red<3><<<16, 256>>>(poly);
    k_post<<<16, 128>>>(poly, ff1W, ff1b);
    k_ff2<<<197, 64>>>(W2, b2, out, out_size);
}

// round 8
// speedup vs baseline: 1.0026x; 1.0026x over previous
#include <cuda_runtime.h>
#include <cuda_bf16.h>

// Quixer quantum transformer block.
// B=16, W=16 words, 8 qubits (DIM=256), 2 ansatz layers (64 gates), DEGREE=3,
// then measure(24) -> ff1(512) -> ff2(50257).

#define VQ   50257
#define EMBQ 512

typedef unsigned long long ull;

// ----------------------------- scratch ------------------------------------
__device__ float2 g_cs[256 * 64];   // per (b,w): (cos(th/2), sin(th/2)) per gate
__device__ float2 g_qcs[32];        // qff gate table (1 layer)
__device__ float2 g_coeffs[16];     // normalized mix coefficients
__device__ float2 g_st[256 * 256];  // per-(b,w) states after sim14
__device__ float2 g_work[16 * 256]; // reduced work state per batch
__device__ float2 g_acc[16 * 256];  // polynomial accumulator
__device__ float  g_fp[16];         // final_probs
__device__ float2 g_hp[512 * 8];    // h packed: hp[k*8+bp] = (h[2bp][k], h[2bp+1][k])

// ----------------------------- f32x2 helpers --------------------------------
__device__ __forceinline__ ull pack2(float a, float b) {
    ull r; asm("mov.b64 %0, {%1, %2};" : "=l"(r) : "f"(a), "f"(b)); return r;
}
__device__ __forceinline__ ull dup2(float a) {
    ull r; asm("mov.b64 %0, {%1, %1};" : "=l"(r) : "f"(a)); return r;
}
__device__ __forceinline__ void ffma2(ull& d, ull a, ull b) {
    asm("fma.rn.f32x2 %0, %1, %2, %0;" : "+l"(d) : "l"(a), "l"(b));
}
__device__ __forceinline__ void unpack2(ull v, float& lo, float& hi) {
    asm("mov.b64 {%0, %1}, %2;" : "=f"(lo), "=f"(hi) : "l"(v));
}

// ----------------------------- gates (128 threads) ---------------------------
// wire w <-> bit (7-w) of amplitude index; stride = 1<<(7-w)
__device__ __forceinline__ void gate_ry(float2* st, float c, float s, int wire) {
    int str = 1 << (7 - wire);
    int p = threadIdx.x;                       // 128 pairs, one per thread
    int i0 = ((p & ~(str - 1)) << 1) | (p & (str - 1));
    int i1 = i0 + str;
    float2 a0 = st[i0], a1 = st[i1];
    st[i0] = make_float2(c * a0.x - s * a1.x, c * a0.y - s * a1.y);
    st[i1] = make_float2(s * a0.x + c * a1.x, s * a0.y + c * a1.y);
    __syncthreads();
}
// controlled RX: [[c,-is],[-is,c]] on target where control bit == 1
__device__ __forceinline__ void gate_crx(float2* st, float c, float s, int cw, int tw) {
    int str = 1 << (7 - tw);
    int cm  = 1 << (7 - cw);
    int p = threadIdx.x;
    int i0 = ((p & ~(str - 1)) << 1) | (p & (str - 1));
    if (i0 & cm) {
        int i1 = i0 + str;
        float2 a0 = st[i0], a1 = st[i1];
        st[i0] = make_float2(c * a0.x + s * a1.y, c * a0.y - s * a1.x);
        st[i1] = make_float2(s * a0.y + c * a1.x, c * a1.y - s * a0.x);
    }
    __syncthreads();
}

__device__ void sim14(float2* st, const float2* cs, int layers) {
    int idx = 0;
    for (int L = 0; L < layers; L++) {
        for (int i = 0; i < 8; i++, idx++)  gate_ry(st, cs[idx].x, cs[idx].y, i);
        for (int i = 7; i >= 0; i--, idx++) gate_crx(st, cs[idx].x, cs[idx].y, i, (i + 1) & 7);
        for (int i = 0; i < 8; i++, idx++)  gate_ry(st, cs[idx].x, cs[idx].y, i);
        for (int i = 0; i < 8; i++, idx++) {          // order: 7, 0, 1, ..., 6
            int ci = (i == 0) ? 7 : (i - 1);
            gate_crx(st, cs[idx].x, cs[idx].y, ci, (ci + 7) & 7);
        }
    }
}

// ----------------------------- k_emb ----------------------------------------
// grid 256 (= b*16+w), 256 threads: wparams = emb @ e2rW^T + b -> (cos,sin)
__global__ void k_emb(const int* __restrict__ x, const float* __restrict__ embW,
                      const float* __restrict__ e2rW, const float* __restrict__ e2rb,
                      const float* __restrict__ mix, const float* __restrict__ qff) {
    __shared__ float emb[EMBQ];
    int tid = threadIdx.x, blk = blockIdx.x;
    int row = x[blk];
    for (int i = tid; i < EMBQ; i += 256) emb[i] = embW[(size_t)row * EMBQ + i];
    __syncthreads();
    int wid = tid >> 5, lane = tid & 31;
    for (int jj = 0; jj < 8; jj++) {
        int j = wid * 8 + jj;
        float p = 0.f;
        const float* wr = e2rW + j * EMBQ;
        for (int k = lane; k < EMBQ; k += 32) p += emb[k] * wr[k];
        #pragma unroll
        for (int o = 16; o; o >>= 1) p += __shfl_xor_sync(0xffffffffu, p, o);
        if (lane == 0) {
            float th = 0.5f * (p + e2rb[j]);
            g_cs[blk * 64 + j] = make_float2(cosf(th), sinf(th));
        }
    }
    if (blk == 0) {
        if (wid == 0) {
            float re = 0.f, im = 0.f, a = 0.f;
            if (lane < 16) { re = mix[2 * lane]; im = mix[2 * lane + 1]; a = sqrtf(re * re + im * im); }
            float s = a;
            #pragma unroll
            for (int o = 16; o; o >>= 1) s += __shfl_xor_sync(0xffffffffu, s, o);
            s = fmaxf(s, 1e-12f);
            if (lane < 16) g_coeffs[lane] = make_float2(re / s, im / s);
        } else if (wid == 1) {
            float th = 0.5f * qff[lane];
            g_qcs[lane] = make_float2(cosf(th), sinf(th));
        }
    }
}

// ----------------------------- k_deg ----------------------------------------
// grid 256 (b*16+w), 128 threads: replicate batch work state, run 2-layer sim14
template <bool FIRST>
__global__ void k_deg() {
    __shared__ float2 st[256];
    __shared__ float2 cs[64];
    int tid = threadIdx.x, blk = blockIdx.x;
    int b = blk >> 4;
    if (FIRST) {
        st[tid]       = make_float2(tid == 0 ? 1.f : 0.f, 0.f);
        st[tid + 128] = make_float2(0.f, 0.f);
    } else {
        st[tid]       = g_work[b * 256 + tid];
        st[tid + 128] = g_work[b * 256 + tid + 128];
    }
    if (tid < 64) cs[tid] = g_cs[blk * 64 + tid];
    __syncthreads();
    sim14(st, cs, 2);
    g_st[blk * 256 + tid]       = st[tid];
    g_st[blk * 256 + tid + 128] = st[tid + 128];
}

// ----------------------------- k_red ----------------------------------------
// grid 16 (batch), 256 threads: word reduction with coeffs + poly accumulate
template <int D>
__global__ void k_red(const float* __restrict__ poly) {
    int i = threadIdx.x, b = blockIdx.x;
    float2 red = make_float2(0.f, 0.f);
    #pragma unroll
    for (int w = 0; w < 16; w++) {
        float2 c = g_coeffs[w];
        float2 s = g_st[(b * 16 + w) * 256 + i];
        red.x += s.x * c.x - s.y * c.y;
        red.y += s.x * c.y + s.y * c.x;
    }
    g_work[b * 256 + i] = red;
    float pd = poly[D];
    float2 a;
    if (D == 1) {
        a = make_float2(pd * red.x + (i == 0 ? poly[0] : 0.f), pd * red.y);
    } else {
        a = g_acc[b * 256 + i];
        a.x += pd * red.x;
        a.y += pd * red.y;
    }
    g_acc[b * 256 + i] = a;
}

// ----------------------------- k_post ---------------------------------------
// grid 16, 128 threads: mixed/normalize, 1-layer sim14, measure XYZ, ff1
__global__ void k_post(const float* __restrict__ poly, const float* __restrict__ ff1W,
                       const float* __restrict__ ff1b) {
    __shared__ float2 st[256];
    __shared__ float2 qcs[32];
    __shared__ float r3[12];
    __shared__ float ex[24];
    int tid = threadIdx.x, b = blockIdx.x;
    int lane = tid & 31, wid = tid >> 5;

    float spoly = fabsf(poly[0]) + fabsf(poly[1]) + fabsf(poly[2]) + fabsf(poly[3]);
    float invp = 1.f / spoly;
    float2 a0 = g_acc[b * 256 + tid];
    float2 a1 = g_acc[b * 256 + tid + 128];
    a0.x *= invp; a0.y *= invp; a1.x *= invp; a1.y *= invp;

    float ns = a0.x * a0.x + a0.y * a0.y + a1.x * a1.x + a1.y * a1.y;
    #pragma unroll
    for (int o = 16; o; o >>= 1) ns += __shfl_xor_sync(0xffffffffu, ns, o);
    if (lane == 0) r3[wid] = ns;
    __syncthreads();
    float fp = sqrtf(r3[0] + r3[1] + r3[2] + r3[3]);
    if (tid == 0) g_fp[b] = fp;
    float inv = 1.f / fmaxf(fp, 1e-12f);
    __syncthreads();  // r3 reuse below

    st[tid]       = make_float2(a0.x * inv, a0.y * inv);
    st[tid + 128] = make_float2(a1.x * inv, a1.y * inv);
    if (tid < 32) qcs[tid] = g_qcs[tid];
    __syncthreads();

    sim14(st, qcs, 1);

    // measure X/Y/Z per wire
    for (int w = 0; w < 8; w++) {
        int str = 1 << (7 - w);
        int i0 = ((tid & ~(str - 1)) << 1) | (tid & (str - 1));
        int i1 = i0 + str;
        float2 A = st[i0], B = st[i1];
        float cr = A.x * B.x + A.y * B.y;
        float ci = A.x * B.y - A.y * B.x;
        float z  = A.x * A.x + A.y * A.y - B.x * B.x - B.y * B.y;
        #pragma unroll
        for (int o = 16; o; o >>= 1) {
            cr += __shfl_xor_sync(0xffffffffu, cr, o);
            ci += __shfl_xor_sync(0xffffffffu, ci, o);
            z  += __shfl_xor_sync(0xffffffffu, z,  o);
        }
        if (lane == 0) { r3[wid] = cr; r3[4 + wid] = ci; r3[8 + wid] = z; }
        __syncthreads();
        if (tid == 0) {
            ex[w]      = 2.f * (r3[0] + r3[1] + r3[2] + r3[3]);
            ex[8 + w]  = 2.f * (r3[4] + r3[5] + r3[6] + r3[7]);
            ex[16 + w] =        r3[8] + r3[9] + r3[10] + r3[11];
        }
        __syncthreads();
    }

    // ff1: h = relu(exps @ ff1W^T + b), write packed pairs for ff2
    for (int j = tid; j < EMBQ; j += 128) {
        float h = ff1b[j];
        const float* wr = ff1W + j * 24;
        #pragma unroll
        for (int m = 0; m < 24; m++) h += ex[m] * wr[m];
        h = fmaxf(h, 0.f);
        float* dst = (float*)&g_hp[j * 8 + (b >> 1)];
        dst[b & 1] = h;
    }
}

// ----------------------------- k_ff2 ----------------------------------------
// op[b][v] = sum_k h[b][k]*W2[v][k] + b2[v].  197 blocks x 64 threads,
// 4 vocab rows/thread, 16 batches packed as 8 f32x2 accumulators.
__global__ void __launch_bounds__(64) k_ff2(const float* __restrict__ W2,
                                            const float* __restrict__ b2,
                                            float* __restrict__ out, int out_size) {
    __shared__ float4 sh[2048];  // hp: per k, 4 float4 = 8 batch pairs
    int tid = threadIdx.x;
    const float4* gp = (const float4*)g_hp;
    for (int i = tid; i < 2048; i += 64) sh[i] = gp[i];
    __syncthreads();

    int base = blockIdx.x * 256;
    int v[4]; bool ok[4];
    #pragma unroll
    for (int r = 0; r < 4; r++) {
        v[r] = base + r * 64 + tid;
        ok[r] = (v[r] < VQ);
        if (!ok[r]) v[r] = VQ - 1;
    }

    ull acc[4][8];
    #pragma unroll
    for (int r = 0; r < 4; r++)
        #pragma unroll
        for (int bp = 0; bp < 8; bp++) acc[r][bp] = 0ull;

    for (int k4 = 0; k4 < 128; k4++) {
        float4 w[4];
        #pragma unroll
        for (int r = 0; r < 4; r++)
            w[r] = *(const float4*)(W2 + (size_t)v[r] * EMBQ + k4 * 4);
        #pragma unroll
        for (int kk = 0; kk < 4; kk++) {
            int k = k4 * 4 + kk;
            ull h[8];
            #pragma unroll
            for (int q = 0; q < 4; q++) {
                float4 f = sh[k * 4 + q];
                h[2 * q]     = pack2(f.x, f.y);
                h[2 * q + 1] = pack2(f.z, f.w);
            }
            #pragma unroll
            for (int r = 0; r < 4; r++) {
                float ws = (kk == 0) ? w[r].x : (kk == 1) ? w[r].y : (kk == 2) ? w[r].z : w[r].w;
                ull wd = dup2(ws);
                #pragma unroll
                for (int bp = 0; bp < 8; bp++) ffma2(acc[r][bp], h[bp], wd);
            }
        }
    }

    #pragma unroll
    for (int r = 0; r < 4; r++) {
        if (!ok[r]) continue;
        float bias = b2[v[r]];
        #pragma unroll
        for (int bp = 0; bp < 8; bp++) {
            float lo, hi;
            unpack2(acc[r][bp], lo, hi);
            out[(size_t)(2 * bp) * VQ + v[r]]     = lo + bias;
            out[(size_t)(2 * bp + 1) * VQ + v[r]] = hi + bias;
        }
    }

    if (blockIdx.x == 0 && tid == 0 && out_size > 16 * VQ) {
        float s = 0.f;
        for (int b = 0; b < 16; b++) s += g_fp[b];
        out[16 * VQ] = s * (1.f / 16.f);
    }
}

// ----------------------------- launch ---------------------------------------
extern "C" void kernel_launch(void* const* d_in, const int* in_sizes, int n_in,
                              void* d_out, int out_size) {
    const int*   x    = (const int*)  d_in[0];
    const float* embW = (const float*)d_in[1];
    const float* e2rW = (const float*)d_in[2];
    const float* e2rb = (const float*)d_in[3];
    const float* poly = (const float*)d_in[4];
    const float* mix  = (const float*)d_in[5];
    const float* qff  = (const float*)d_in[6];
    const float* ff1W = (const float*)d_in[7];
    const float* ff1b = (const float*)d_in[8];
    const float* W2   = (const float*)d_in[9];
    const float* b2   = (const float*)d_in[10];
    float* out = (float*)d_out;

    k_emb<<<256, 256>>>(x, embW, e2rW, e2rb, mix, qff);
    k_deg<true><<<256, 128>>>();
    k_red<1><<<16, 256>>>(poly);
    k_deg<false><<<256, 128>>>();
    k_red<2><<<16, 256>>>(poly);
    k_deg<false><<<256, 128>>>();
    k_red<3><<<16, 256>>>(poly);
    k_post<<<16, 128>>>(poly, ff1W, ff1b);
    k_ff2<<<197, 64>>>(W2, b2, out, out_size);
}